// round 1
// baseline (speedup 1.0000x reference)
#include <cuda_runtime.h>

// Problem constants: inputs [4,320,320,2] f32, output [4,320,320,6] f32.
// 8 "images" = batch(4) x channel(2), each 320x320.
#define NB   4
#define NH   320
#define NW   320
#define NIMG 8
#define BIGV 1e5f

// Scratch for per-image squared 1D column distances g2[img][h][w].
__device__ float g2_scratch[NIMG * NH * NW];

// -------------------------------------------------------------------------
// Kernel 1: column pass. For each (img, w) column, compute
//   g[h] = min( dist to nearest seed above, dist below, BIG ), store g^2.
// Seeds: pixels where uint8((1-x)*127.5) == 0  <=>  (1-x)*127.5 < 1.
// grid: (NIMG, NW/64), block: 64 threads (one per w).
// -------------------------------------------------------------------------
__global__ void __launch_bounds__(64) col_pass_kernel(const float* __restrict__ in) {
    const int img = blockIdx.x;            // 0..7
    const int w   = blockIdx.y * 64 + threadIdx.x;
    const int b   = img >> 1;
    const int c   = img & 1;

    const float* __restrict__ base = in + (((size_t)b * NH) * NW + w) * 2 + c;
    float* __restrict__ sc = g2_scratch + (size_t)img * NH * NW + w;

    // Forward: distance to nearest seed at h' <= h  (h - last). No seed -> h + BIG.
    float last = -BIGV;
    #pragma unroll 4
    for (int h = 0; h < NH; ++h) {
        float x = base[(size_t)h * (NW * 2)];
        // uint8 truncation of (1-x)*127.5, value in (0,127.5]: zero iff < 1
        bool zero = ((1.0f - x) * 127.5f) < 1.0f;
        if (zero) last = (float)h;
        sc[h * NW] = (float)h - last;      // ==0 exactly iff seed at h
    }

    // Backward: combine with distance to nearest seed at h' >= h, cap, square.
    float nxt = 2.0f * BIGV;
    #pragma unroll 4
    for (int h = NH - 1; h >= 0; --h) {
        float t = sc[h * NW];
        if (t == 0.0f) nxt = (float)h;     // seed marker from forward pass
        float g = fminf(fminf(t, nxt - (float)h), BIGV);
        sc[h * NW] = g * g;
    }
}

// -------------------------------------------------------------------------
// Kernel 2: row pass + epilogue. One block per (b,h) pixel-row; handles BOTH
// channels (their g2 rows share the (j-x)^2 term). Each thread owns one j and
// scans all 320 source columns x from shared memory (float4 loads, broadcast
// -> conflict-free). Then 3 Gaussians per channel, interleaved store.
// grid: NB*NH blocks, block: 320 threads.
// -------------------------------------------------------------------------
__global__ void __launch_bounds__(320) row_pass_kernel(float* __restrict__ out) {
    const int bh = blockIdx.x;             // b*320 + h
    const int j  = threadIdx.x;            // 0..319
    const int b  = bh / NH;
    const int h  = bh - b * NH;

    __shared__ __align__(16) float sh0[NW];
    __shared__ __align__(16) float sh1[NW];

    const float* __restrict__ r0 = g2_scratch + (((size_t)(b * 2 + 0) * NH) + h) * NW;
    const float* __restrict__ r1 = g2_scratch + (((size_t)(b * 2 + 1) * NH) + h) * NW;
    sh0[j] = r0[j];
    sh1[j] = r1[j];
    __syncthreads();

    const float fj = (float)j;
    float m0 = 1e30f;
    float m1 = 1e30f;

    const float4* __restrict__ v0 = (const float4*)sh0;
    const float4* __restrict__ v1 = (const float4*)sh1;

    #pragma unroll 8
    for (int xb = 0; xb < NW / 4; ++xb) {
        float4 a  = v0[xb];
        float4 bb = v1[xb];
        float d0 = fj - (float)(4 * xb);
        float d1 = d0 - 1.0f;
        float d2 = d0 - 2.0f;
        float d3 = d0 - 3.0f;
        m0 = fminf(m0, fmaf(d0, d0, a.x));
        m0 = fminf(m0, fmaf(d1, d1, a.y));
        m0 = fminf(m0, fmaf(d2, d2, a.z));
        m0 = fminf(m0, fmaf(d3, d3, a.w));
        m1 = fminf(m1, fmaf(d0, d0, bb.x));
        m1 = fminf(m1, fmaf(d1, d1, bb.y));
        m1 = fminf(m1, fmaf(d2, d2, bb.z));
        m1 = fminf(m1, fmaf(d3, d3, bb.w));
    }

    // sigmas = [0.02, 0.08, 0.16] * 320 -> denom = 2*sigma^2 = [81.92, 1310.72, 5242.88]
    const float inv0 = 1.0f / 81.92f;
    const float inv1 = 1.0f / 1310.72f;
    const float inv2 = 1.0f / 5242.88f;

    float* __restrict__ o = out + ((size_t)bh * NW + j) * 6;
    o[0] = __expf(-m0 * inv0);
    o[1] = __expf(-m0 * inv1);
    o[2] = __expf(-m0 * inv2);
    o[3] = __expf(-m1 * inv0);
    o[4] = __expf(-m1 * inv1);
    o[5] = __expf(-m1 * inv2);
}

extern "C" void kernel_launch(void* const* d_in, const int* in_sizes, int n_in,
                              void* d_out, int out_size) {
    const float* in = (const float*)d_in[0];
    float* out = (float*)d_out;
    (void)in_sizes; (void)n_in; (void)out_size;

    dim3 g1(NIMG, NW / 64);
    col_pass_kernel<<<g1, 64>>>(in);
    row_pass_kernel<<<NB * NH, NW>>>(out);
}

// round 3
// speedup vs baseline: 2.8562x; 2.8562x over previous
#include <cuda_runtime.h>

// inputs [4,320,320,2] f32 -> output [4,320,320,6] f32
#define NB   4
#define NH   320
#define NW   320
#define NIMG 8

// Scratch: per-image squared 1D column distances g2[img][h][w].
__device__ float g2_scratch[NIMG * NH * NW];

// -------------------------------------------------------------------------
// Kernel 1: column pass, fused fwd+bwd through shared memory.
// grid (NIMG, NW/64), block 64 threads (one per column w).
// Fwd: track last seed index (int16, sentinel -32768), store to smem.
// Bwd: nearest seed below, combine, write g2 to global scratch.
// Seed: uint8((1-x)*127.5) == 0  <=>  (1-x)*127.5 < 1.
// Sentinel note: "no seed" sides give g ~ 3.3e4 instead of the reference's
// 1e5 cap; both square to values whose exp() underflows to exactly 0 for all
// three sigmas, and neither can ever beat a real candidate (<= 2*320^2),
// so outputs are identical.
// -------------------------------------------------------------------------
#define CTW 64

__global__ void __launch_bounds__(CTW) col_pass_kernel(const float* __restrict__ in) {
    __shared__ short smLast[NH * CTW];   // 40 KB

    const int img = blockIdx.x;          // 0..7
    const int wt  = threadIdx.x;         // 0..63
    const int w   = blockIdx.y * CTW + wt;
    const int b   = img >> 1;
    const int c   = img & 1;

    const float* __restrict__ base = in + (((size_t)b * NH) * NW + w) * 2 + c;

    // Forward scan with batched loads for MLP.
    int last = -32768;
    #pragma unroll
    for (int hb = 0; hb < NH; hb += 32) {
        float v[32];
        #pragma unroll
        for (int u = 0; u < 32; ++u)
            v[u] = base[(size_t)(hb + u) * (NW * 2)];
        #pragma unroll
        for (int u = 0; u < 32; ++u) {
            int h = hb + u;
            if ((1.0f - v[u]) * 127.5f < 1.0f) last = h;
            smLast[h * CTW + wt] = (short)last;
        }
    }

    // Backward scan: combine up/down distances, square, write scratch.
    float* __restrict__ sc = g2_scratch + (size_t)img * NH * NW + w;
    int nxt = 40000;
    #pragma unroll 8
    for (int h = NH - 1; h >= 0; --h) {
        int lastv = smLast[h * CTW + wt];
        if (lastv == h) nxt = h;
        int up   = h - lastv;
        int down = nxt - h;
        float g = (float)min(up, down);
        sc[(size_t)h * NW] = g * g;
    }
}

// -------------------------------------------------------------------------
// Kernel 2: row pass with exact outward-expanding pruned search + epilogue.
// One block per (b,h) row, both channels together. Each thread owns pixel j,
// evaluates 4-wide x-tiles outward from j, and stops a side as soon as the
// pure geometric distance already exceeds the current min (exact pruning).
// grid NB*NH, block 320.
// -------------------------------------------------------------------------
__global__ void __launch_bounds__(NW) row_pass_kernel(float* __restrict__ out) {
    const int bh = blockIdx.x;           // b*320 + h
    const int j  = threadIdx.x;
    const int b  = bh / NH;
    const int h  = bh - b * NH;

    __shared__ __align__(16) float sh0[NW];
    __shared__ __align__(16) float sh1[NW];

    sh0[j] = g2_scratch[(((size_t)(b * 2 + 0) * NH) + h) * NW + j];
    sh1[j] = g2_scratch[(((size_t)(b * 2 + 1) * NH) + h) * NW + j];
    __syncthreads();

    const float4* __restrict__ v0 = (const float4*)sh0;
    const float4* __restrict__ v1 = (const float4*)sh1;

    const float fj = (float)j;
    float m0 = 3e38f, m1 = 3e38f;

    // Evaluate one 4-wide tile for both channels.
    auto evalTile = [&](int tb) {
        float4 a = v0[tb];
        float4 c = v1[tb];
        float d0 = fj - (float)(tb * 4);
        float d1 = d0 - 1.0f;
        float d2 = d0 - 2.0f;
        float d3 = d0 - 3.0f;
        m0 = fminf(m0, fmaf(d0, d0, a.x));
        m0 = fminf(m0, fmaf(d1, d1, a.y));
        m0 = fminf(m0, fmaf(d2, d2, a.z));
        m0 = fminf(m0, fmaf(d3, d3, a.w));
        m1 = fminf(m1, fmaf(d0, d0, c.x));
        m1 = fminf(m1, fmaf(d1, d1, c.y));
        m1 = fminf(m1, fmaf(d2, d2, c.z));
        m1 = fminf(m1, fmaf(d3, d3, c.w));
    };

    const int tb0 = j >> 2;
    evalTile(tb0);

    int tl = tb0 - 1;
    int tr = tb0 + 1;
    float dL = fj - (float)(4 * tl + 3);   // min distance into left tile
    float dR = (float)(4 * tr) - fj;       // min distance into right tile
    bool doneL = (tl < 0);
    bool doneR = (tr >= NW / 4);

    while (!(doneL && doneR)) {
        float mM = fmaxf(m0, m1);
        if (!doneL) {
            if (dL * dL > mM) {
                doneL = true;
            } else {
                evalTile(tl);
                --tl; dL += 4.0f;
                doneL = (tl < 0);
            }
        }
        if (!doneR) {
            if (dR * dR > mM) {
                doneR = true;
            } else {
                evalTile(tr);
                ++tr; dR += 4.0f;
                doneR = (tr >= NW / 4);
            }
        }
    }

    // sigmas = [0.02,0.08,0.16]*320 -> 2*sigma^2 = [81.92, 1310.72, 5242.88]
    const float inv0 = 1.0f / 81.92f;
    const float inv1 = 1.0f / 1310.72f;
    const float inv2 = 1.0f / 5242.88f;

    float* __restrict__ o = out + ((size_t)bh * NW + j) * 6;
    float2 p0 = make_float2(__expf(-m0 * inv0), __expf(-m0 * inv1));
    float2 p1 = make_float2(__expf(-m0 * inv2), __expf(-m1 * inv0));
    float2 p2 = make_float2(__expf(-m1 * inv1), __expf(-m1 * inv2));
    ((float2*)o)[0] = p0;
    ((float2*)o)[1] = p1;
    ((float2*)o)[2] = p2;
}

extern "C" void kernel_launch(void* const* d_in, const int* in_sizes, int n_in,
                              void* d_out, int out_size) {
    const float* in = (const float*)d_in[0];
    float* out = (float*)d_out;
    (void)in_sizes; (void)n_in; (void)out_size;

    dim3 g1(NIMG, NW / CTW);
    col_pass_kernel<<<g1, CTW>>>(in);
    row_pass_kernel<<<NB * NH, NW>>>(out);
}